// round 11
// baseline (speedup 1.0000x reference)
#include <cuda_runtime.h>
#include <cuda_bf16.h>
#include <cstdint>

#define DIM 256
#define NMOD 5
#define NROWS 16384
#define XPITCH (NMOD * DIM)

#define APITCH 264            // A_s pitch (bf16)
#define BPITCH 72             // B pitch (bf16), 64 K-cols + 8 pad
#define CHUNK_BYTES (256 * BPITCH * 2)     // 36864
#define CHUNK_ELEM  (256 * BPITCH)         // 18432
#define BFULL_BYTES (4 * CHUNK_BYTES)      // 147456
#define BFULL_U16   (BFULL_BYTES / 16)     // 9216

// Fused per-branch matrices, PRE-PADDED image: chunk c = n*4+kc holds
// [256 N-rows][72 cols (64 K + 8 pad)] bf16 -> contiguous cp.async.
__device__ __align__(16) __nv_bfloat16 g_M[NMOD * 4][256][BPITCH];
__device__ float g_c[NMOD][DIM];
// branch outputs workspace (bf16)
__device__ __align__(16) __nv_bfloat16 g_ab[NMOD][NROWS][DIM];

// ---------------- helpers ----------------
__device__ __forceinline__ void ldsm_x4(uint32_t* r, const void* p) {
    uint32_t addr = (uint32_t)__cvta_generic_to_shared(p);
    asm volatile("ldmatrix.sync.aligned.m8n8.x4.shared.b16 {%0,%1,%2,%3}, [%4];"
                 : "=r"(r[0]), "=r"(r[1]), "=r"(r[2]), "=r"(r[3]) : "r"(addr));
}
__device__ __forceinline__ void mma16816(float* d, const uint32_t* a, const uint32_t* b) {
    asm volatile("mma.sync.aligned.m16n8k16.row.col.f32.bf16.bf16.f32 "
                 "{%0,%1,%2,%3},{%4,%5,%6,%7},{%8,%9},{%0,%1,%2,%3};"
                 : "+f"(d[0]), "+f"(d[1]), "+f"(d[2]), "+f"(d[3])
                 : "r"(a[0]), "r"(a[1]), "r"(a[2]), "r"(a[3]), "r"(b[0]), "r"(b[1]));
}
__device__ __forceinline__ float warp_sum(float v) {
#pragma unroll
    for (int o = 16; o; o >>= 1) v += __shfl_xor_sync(0xffffffffu, v, o);
    return v;
}
__device__ __forceinline__ void cp_async16(void* smem, const void* g) {
    uint32_t s = (uint32_t)__cvta_generic_to_shared(smem);
    asm volatile("cp.async.cg.shared.global [%0], [%1], 16;\n" :: "r"(s), "l"(g));
}
__device__ __forceinline__ void cp_commit() { asm volatile("cp.async.commit_group;\n"); }
__device__ __forceinline__ void cp_wait0() { asm volatile("cp.async.wait_group 0;\n"); }

// ------------------------------------------------------------------
// prologue: M_n = Wo_n @ Wv_n (bf16 mma, single smem phase) + c_n bias.
// grid (8, 5): bx = 32-row d-block, by = n. 256 threads, warp tile 16x64.
// smem: A_s [32][264] bf16 @0 ; BF [256 k][264 j] bf16 @16896 ; bv @152064
// ------------------------------------------------------------------
constexpr int PSM_BF = 16896;
constexpr int PSM_BV = PSM_BF + 256 * APITCH * 2;   // 152064
constexpr int PSM_TOTAL = PSM_BV + 1024;            // 153088

__global__ __launch_bounds__(256, 1)
void fuse_weights_kernel(const float* __restrict__ sWi, const float* __restrict__ sbi,
                         const float* __restrict__ sWo, const float* __restrict__ sbo,
                         const float* __restrict__ cWi, const float* __restrict__ cbi,
                         const float* __restrict__ cWo, const float* __restrict__ cbo) {
    extern __shared__ char sm[];
    __nv_bfloat16* A_s = (__nv_bfloat16*)sm;                // [32][APITCH]
    __nv_bfloat16* BF  = (__nv_bfloat16*)(sm + PSM_BF);     // [256 k][APITCH j]
    float* bv_s = (float*)(sm + PSM_BV);                    // [256]
    float* bred = (float*)(sm + PSM_BF);                    // reuse after GEMM

    const int n = blockIdx.y, bx = blockIdx.x;
    const float* Wo = (n == 0) ? sWo : cWo + (size_t)(n - 1) * DIM * DIM;
    const float* Wv = (n == 0) ? sWi + 2 * DIM * DIM
                               : cWi + (size_t)(n - 1) * 3 * DIM * DIM + 2 * DIM * DIM;
    const float* bv = (n == 0) ? sbi + 2 * DIM : cbi + (size_t)(n - 1) * 3 * DIM + 2 * DIM;
    const float* bo = (n == 0) ? sbo : cbo + (size_t)(n - 1) * DIM;

    const int tid = threadIdx.x;
    const int w = tid >> 5, l = tid & 31;
    const int wm = w & 1, wn = w >> 1;
    const int lq = l >> 2, lr = l & 3;

    bv_s[tid] = bv[tid];

    // A tile: Wo rows bx*32..+31, all 256 cols -> bf16
#pragma unroll
    for (int i = 0; i < 8; i++) {
        int e = tid + i * 256, r = e >> 6, c4 = (e & 63) << 2;
        float4 v = *(const float4*)(Wo + (size_t)(bx * 32 + r) * DIM + c4);
        __nv_bfloat16* dst = A_s + r * APITCH + c4;
        *(__nv_bfloat162*)(dst)     = __floats2bfloat162_rn(v.x, v.y);
        *(__nv_bfloat162*)(dst + 2) = __floats2bfloat162_rn(v.z, v.w);
    }

    // BF[k][j] = Wv[j][k], full 256x256. j = lane (conflict-free STS), k4 per iter.
#pragma unroll 1
    for (int i = 0; i < 64; i++) {
        int j = tid & 255;
        int k4 = i * 4;
        float4 v = *(const float4*)(Wv + (size_t)j * DIM + k4);
        BF[(k4 + 0) * APITCH + j] = __float2bfloat16(v.x);
        BF[(k4 + 1) * APITCH + j] = __float2bfloat16(v.y);
        BF[(k4 + 2) * APITCH + j] = __float2bfloat16(v.z);
        BF[(k4 + 3) * APITCH + j] = __float2bfloat16(v.w);
    }
    __syncthreads();

    float cf[8][4];
#pragma unroll
    for (int nt = 0; nt < 8; nt++)
#pragma unroll
        for (int i = 0; i < 4; i++) cf[nt][i] = 0.f;

#pragma unroll
    for (int ks = 0; ks < 16; ks++) {
        uint32_t af[4];
        {
            int row = wm * 16 + (l & 7) + ((l >> 3) & 1) * 8;
            int col = ks * 16 + (l >> 4) * 8;
            ldsm_x4(af, A_s + row * APITCH + col);
        }
        uint32_t bfr[8][2];
#pragma unroll
        for (int np = 0; np < 4; np++) {
            int row = wn * 64 + np * 16 + (l & 7) + (l >> 4) * 8;
            int col = ks * 16 + ((l >> 3) & 1) * 8;
            uint32_t r4[4];
            ldsm_x4(r4, BF + row * APITCH + col);
            bfr[2 * np][0] = r4[0]; bfr[2 * np][1] = r4[1];
            bfr[2 * np + 1][0] = r4[2]; bfr[2 * np + 1][1] = r4[3];
        }
#pragma unroll
        for (int nt = 0; nt < 8; nt++)
            mma16816(cf[nt], af, bfr[nt]);
    }
    __syncthreads();   // BF reads done (bred reuses it)

    // store to padded image: chunk = n*4 + (k>>6), row = d, col = k&63
#pragma unroll
    for (int nt = 0; nt < 8; nt++) {
        int d = bx * 32 + wm * 16 + lq;
        int k = wn * 64 + nt * 8 + 2 * lr;
        int ch = n * 4 + (k >> 6);
        int col = k & 63;
        *(__nv_bfloat162*)&g_M[ch][d][col]     = __floats2bfloat162_rn(cf[nt][0], cf[nt][1]);
        *(__nv_bfloat162*)&g_M[ch][d + 8][col] = __floats2bfloat162_rn(cf[nt][2], cf[nt][3]);
    }

    // bias: c[d] = Wo[d,:] @ bv + bo[d]
    {
        int row = tid & 31, part = tid >> 5;
        float s = 0.f;
#pragma unroll 8
        for (int j = 0; j < 32; j++) {
            int jj = part * 32 + j;
            s += __bfloat162float(A_s[row * APITCH + jj]) * bv_s[jj];
        }
        bred[part * 32 + row] = s;
        __syncthreads();
        if (tid < 32) {
            float c = bo[bx * 32 + tid];
#pragma unroll
            for (int p = 0; p < 8; p++) c += bred[p * 32 + tid];
            g_c[n][bx * 32 + tid] = c;
        }
    }
}

// ------------------------------------------------------------------
// persistent GEMM: grid 148, 512 threads (16 warps, 4Mx4N, warp tile 16x64).
// smem: full B (4 chunks, 147456 B) resident + double-buffered 64-row A.
// Work items: item = n*256 + tile (n-major contiguous ranges -> <=2 B loads/CTA).
// ------------------------------------------------------------------
constexpr int GSM_B = 0;                                // 147456
constexpr int GSM_A = BFULL_BYTES;                      // 2 x 33792 = 67584
constexpr int GSM_TOTAL = GSM_A + 2 * 64 * APITCH * 2;  // 215040
#define NITEMS 1280
#define NCTAS 148

__global__ __launch_bounds__(512, 1)
void gemm_kernel(const float* __restrict__ x, const int* __restrict__ modal_idx) {
    extern __shared__ char sm[];
    __nv_bfloat16* B_s = (__nv_bfloat16*)(sm + GSM_B);   // [4][256][BPITCH]
    __nv_bfloat16* A_s = (__nv_bfloat16*)(sm + GSM_A);   // [2][64][APITCH]

    const int tid = threadIdx.x;
    const int w = tid >> 5, l = tid & 31;
    const int wm = w & 3, wn = w >> 2;
    const int lq = l >> 2, lr = l & 3;
    const int mi = *modal_idx;

    // contiguous item range: first 96 CTAs get 9 items, rest 8  (96*9+52*8=1280)
    const int c = blockIdx.x;
    const int base = c * 8 + (c < 96 ? c : 96);
    const int count = (c < 96) ? 9 : 8;

    int cur_n = -1;

    // prefill A[0] for item 'base'
    {
        int n0 = base >> 8, t0 = base & 255;
        int mod = (n0 == 0) ? mi : (((n0 - 1) < mi) ? (n0 - 1) : n0);
        const float* src = x + (size_t)(t0 * 64) * XPITCH + mod * DIM;
#pragma unroll
        for (int i = 0; i < 8; i++) {
            int e = tid + i * 512, r = e >> 6, c4 = (e & 63) << 2;
            float4 v = *(const float4*)(src + (size_t)r * XPITCH + c4);
            __nv_bfloat16* dst = A_s + r * APITCH + c4;
            *(__nv_bfloat162*)(dst)     = __floats2bfloat162_rn(v.x, v.y);
            *(__nv_bfloat162*)(dst + 2) = __floats2bfloat162_rn(v.z, v.w);
        }
    }

#pragma unroll 1
    for (int li = 0; li < count; li++) {
        const int item = base + li;
        const int n = item >> 8, tile = item & 255;
        const int r0 = tile * 64;

        // B reload on branch change (<=2 per CTA)
        if (n != cur_n) {
            __syncthreads();   // everyone done reading old B
            const char* src = (const char*)g_M + (size_t)(n * 4) * CHUNK_BYTES;
#pragma unroll
            for (int i = 0; i < 18; i++) {
                int e = tid + i * 512;
                cp_async16((char*)sm + GSM_B + e * 16, src + e * 16);
            }
            cp_commit();
            cp_wait0();
            cur_n = n;
        }

        __syncthreads();   // A[li&1] fill visible; prev mma done on A[(li+1)&1]; B visible

        // fill A for item li+1 (overlaps with mma below via scoreboard)
        if (li + 1 < count) {
            int item2 = item + 1;
            int n2 = item2 >> 8, t2 = item2 & 255;
            int mod2 = (n2 == 0) ? mi : (((n2 - 1) < mi) ? (n2 - 1) : n2);
            const float* src = x + (size_t)(t2 * 64) * XPITCH + mod2 * DIM;
            __nv_bfloat16* Ad = A_s + ((li + 1) & 1) * (64 * APITCH);
#pragma unroll
            for (int i = 0; i < 8; i++) {
                int e = tid + i * 512, r = e >> 6, c4 = (e & 63) << 2;
                float4 v = *(const float4*)(src + (size_t)r * XPITCH + c4);
                __nv_bfloat16* dst = Ad + r * APITCH + c4;
                *(__nv_bfloat162*)(dst)     = __floats2bfloat162_rn(v.x, v.y);
                *(__nv_bfloat162*)(dst + 2) = __floats2bfloat162_rn(v.z, v.w);
            }
        }

        // MMA sweep: K = 256 in 16 ks steps, no barriers
        const __nv_bfloat16* Ac = A_s + (li & 1) * (64 * APITCH);
        float cf[8][4];
#pragma unroll
        for (int nt = 0; nt < 8; nt++)
#pragma unroll
            for (int i = 0; i < 4; i++) cf[nt][i] = 0.f;

#pragma unroll
        for (int ks = 0; ks < 16; ks++) {
            uint32_t af[4];
            {
                int row = wm * 16 + (l & 7) + ((l >> 3) & 1) * 8;
                int col = ks * 16 + (l >> 4) * 8;
                ldsm_x4(af, Ac + row * APITCH + col);
            }
            const __nv_bfloat16* Bch = B_s + (ks >> 2) * CHUNK_ELEM;
            int bcol = (ks & 3) * 16 + ((l >> 3) & 1) * 8;
            uint32_t bfr[8][2];
#pragma unroll
            for (int np = 0; np < 4; np++) {
                int row = wn * 64 + np * 16 + (l & 7) + (l >> 4) * 8;
                uint32_t r4[4];
                ldsm_x4(r4, Bch + row * BPITCH + bcol);
                bfr[2 * np][0] = r4[0]; bfr[2 * np][1] = r4[1];
                bfr[2 * np + 1][0] = r4[2]; bfr[2 * np + 1][1] = r4[3];
            }
#pragma unroll
            for (int nt = 0; nt < 8; nt++)
                mma16816(cf[nt], af, bfr[nt]);
        }

        // store bf16
#pragma unroll
        for (int nt = 0; nt < 8; nt++) {
            int row = wm * 16 + lq;
            int col = wn * 64 + nt * 8 + 2 * lr;
            *(__nv_bfloat162*)&g_ab[n][r0 + row][col]     = __floats2bfloat162_rn(cf[nt][0], cf[nt][1]);
            *(__nv_bfloat162*)&g_ab[n][r0 + row + 8][col] = __floats2bfloat162_rn(cf[nt][2], cf[nt][3]);
        }
    }
}

// ------------------------------------------------------------------
// epilogue kernel: gates + gated LN combine + final LN. grid 512 (32 rows),
// 256 threads (8 warps, 4 rows/warp). Column mapping: pairs 2l+64*jj+{0,1}.
// ------------------------------------------------------------------
__global__ __launch_bounds__(256)
void epilogue_kernel(const float* __restrict__ x,
                     const float* __restrict__ cross_ln_g, const float* __restrict__ cross_ln_b,
                     const float* __restrict__ gate_ln_g, const float* __restrict__ gate_ln_b,
                     const float* __restrict__ gate_W, const float* __restrict__ gate_b,
                     const float* __restrict__ final_ln_g, const float* __restrict__ final_ln_b,
                     const int* __restrict__ modal_idx, float* __restrict__ out) {
    __shared__ float gw_s[1792];   // gate_W 1280 | gate_ln_g 256 | gate_ln_b 256

    const int tid = threadIdx.x;
    const int w = tid >> 5, l = tid & 31;
    const int mi = *modal_idx;

    for (int i = tid; i < 1792; i += 256)
        gw_s[i] = (i < 1280) ? gate_W[i] : (i < 1536 ? gate_ln_g[i - 1280] : gate_ln_b[i - 1536]);
    float gb[5];
#pragma unroll
    for (int n = 0; n < 5; n++) gb[n] = gate_b[n];
    __syncthreads();

#pragma unroll 1
    for (int ri = 0; ri < 4; ri++) {
        const int r = blockIdx.x * 32 + w * 4 + ri;
        const float* qr = x + (size_t)r * XPITCH + mi * DIM;

        float q[8];
        float sum = 0.f, sq = 0.f;
#pragma unroll
        for (int jj = 0; jj < 4; jj++) {
            float2 qq = *(const float2*)(qr + 2 * l + 64 * jj);
            q[2 * jj] = qq.x; q[2 * jj + 1] = qq.y;
            sum += qq.x + qq.y; sq += qq.x * qq.x + qq.y * qq.y;
        }
        sum = warp_sum(sum); sq = warp_sum(sq);
        float m = sum * (1.f / DIM);
        float rs = rsqrtf(fmaxf(sq * (1.f / DIM) - m * m, 0.f) + 1e-5f);

        // gates
        float g[5];
        {
            float lnv[8];
#pragma unroll
            for (int jj = 0; jj < 4; jj++) {
                int cc = 2 * l + 64 * jj;
                float2 gg = *(const float2*)(gw_s + 1280 + cc);
                float2 bb = *(const float2*)(gw_s + 1536 + cc);
                lnv[2 * jj]     = (q[2 * jj] - m) * rs * gg.x + bb.x;
                lnv[2 * jj + 1] = (q[2 * jj + 1] - m) * rs * gg.y + bb.y;
            }
#pragma unroll
            for (int n = 0; n < 5; n++) {
                float s = 0.f;
#pragma unroll
                for (int jj = 0; jj < 4; jj++) {
                    int cc = 2 * l + 64 * jj;
                    float2 ww = *(const float2*)(gw_s + n * DIM + cc);
                    s += lnv[2 * jj] * ww.x + lnv[2 * jj + 1] * ww.y;
                }
                g[n] = warp_sum(s) + gb[n];
            }
            float mx = g[0];
#pragma unroll
            for (int n = 1; n < 5; n++) mx = fmaxf(mx, g[n]);
            float es = 0.f;
#pragma unroll
            for (int n = 0; n < 5; n++) { g[n] = expf(g[n] - mx); es += g[n]; }
            float inv = 1.f / es;
#pragma unroll
            for (int n = 0; n < 5; n++) g[n] *= inv;
        }

        // acc = g0 * (a0 + c0)
        float acc[8];
#pragma unroll
        for (int jj = 0; jj < 4; jj++) {
            int cc = 2 * l + 64 * jj;
            __nv_bfloat162 a2 = *(const __nv_bfloat162*)&g_ab[0][r][cc];
            float2 c2 = *(const float2*)(g_c[0] + cc);
            acc[2 * jj]     = g[0] * (__bfloat162float(a2.x) + c2.x);
            acc[2 * jj + 1] = g[0] * (__bfloat162float(a2.y) + c2.y);
        }

        // cross branches
#pragma unroll 1
        for (int n = 1; n < 5; n++) {
            float t[8], s = 0.f, ss = 0.f;
#pragma unroll
            for (int jj = 0; jj < 4; jj++) {
                int cc = 2 * l + 64 * jj;
                __nv_bfloat162 a2 = *(const __nv_bfloat162*)&g_ab[n][r][cc];
                float2 c2 = *(const float2*)(g_c[n] + cc);
                float t0 = q[2 * jj] + __bfloat162float(a2.x) + c2.x;
                float t1 = q[2 * jj + 1] + __bfloat162float(a2.y) + c2.y;
                t[2 * jj] = t0; t[2 * jj + 1] = t1;
                s += t0 + t1; ss += t0 * t0 + t1 * t1;
            }
            s = warp_sum(s); ss = warp_sum(ss);
            float mn = s * (1.f / DIM);
            float rn = rsqrtf(fmaxf(ss * (1.f / DIM) - mn * mn, 0.f) + 1e-5f);
            const float* gam = cross_ln_g + (n - 1) * DIM;
            const float* bet = cross_ln_b + (n - 1) * DIM;
#pragma unroll
            for (int jj = 0; jj < 4; jj++) {
                int cc = 2 * l + 64 * jj;
                float2 g2 = *(const float2*)(gam + cc);
                float2 b2 = *(const float2*)(bet + cc);
                acc[2 * jj]     += g[n] * ((t[2 * jj] - mn) * rn * g2.x + b2.x);
                acc[2 * jj + 1] += g[n] * ((t[2 * jj + 1] - mn) * rn * g2.y + b2.y);
            }
        }

        // final LN(q + acc)
        float s = 0.f, ss = 0.f;
#pragma unroll
        for (int j = 0; j < 8; j++) {
            acc[j] += q[j];
            s += acc[j]; ss += acc[j] * acc[j];
        }
        s = warp_sum(s); ss = warp_sum(ss);
        float mf = s * (1.f / DIM);
        float rf = rsqrtf(fmaxf(ss * (1.f / DIM) - mf * mf, 0.f) + 1e-5f);
        float* orow = out + (size_t)r * DIM;
#pragma unroll
        for (int jj = 0; jj < 4; jj++) {
            int cc = 2 * l + 64 * jj;
            float2 g2 = *(const float2*)(final_ln_g + cc);
            float2 b2 = *(const float2*)(final_ln_b + cc);
            float2 o;
            o.x = (acc[2 * jj] - mf) * rf * g2.x + b2.x;
            o.y = (acc[2 * jj + 1] - mf) * rf * g2.y + b2.y;
            *(float2*)(orow + cc) = o;
        }
    }
}

// ------------------------------------------------------------------
extern "C" void kernel_launch(void* const* d_in, const int* in_sizes, int n_in,
                              void* d_out, int out_size) {
    (void)in_sizes; (void)n_in; (void)out_size;
    const float* x          = (const float*)d_in[0];
    const float* self_Wi    = (const float*)d_in[1];
    const float* self_bi    = (const float*)d_in[2];
    const float* self_Wo    = (const float*)d_in[3];
    const float* self_bo    = (const float*)d_in[4];
    const float* cross_Wi   = (const float*)d_in[5];
    const float* cross_bi   = (const float*)d_in[6];
    const float* cross_Wo   = (const float*)d_in[7];
    const float* cross_bo   = (const float*)d_in[8];
    const float* cross_ln_g = (const float*)d_in[9];
    const float* cross_ln_b = (const float*)d_in[10];
    const float* gate_ln_g  = (const float*)d_in[11];
    const float* gate_ln_b  = (const float*)d_in[12];
    const float* gate_W     = (const float*)d_in[13];
    const float* gate_b     = (const float*)d_in[14];
    const float* final_ln_g = (const float*)d_in[15];
    const float* final_ln_b = (const float*)d_in[16];
    const int*   modal_idx  = (const int*)d_in[17];
    float* out = (float*)d_out;

    static bool attr_set = false;
    if (!attr_set) {
        cudaFuncSetAttribute(fuse_weights_kernel,
                             cudaFuncAttributeMaxDynamicSharedMemorySize, PSM_TOTAL);
        cudaFuncSetAttribute(gemm_kernel,
                             cudaFuncAttributeMaxDynamicSharedMemorySize, GSM_TOTAL);
        attr_set = true;
    }

    fuse_weights_kernel<<<dim3(8, 5), 256, PSM_TOTAL>>>(self_Wi, self_bi, self_Wo, self_bo,
                                                        cross_Wi, cross_bi, cross_Wo, cross_bo);
    gemm_kernel<<<NCTAS, 512, GSM_TOTAL>>>(x, modal_idx);
    epilogue_kernel<<<512, 256>>>(x, cross_ln_g, cross_ln_b, gate_ln_g, gate_ln_b,
                                  gate_W, gate_b, final_ln_g, final_ln_b, modal_idx, out);
}

// round 12
// speedup vs baseline: 1.0954x; 1.0954x over previous
#include <cuda_runtime.h>
#include <cuda_bf16.h>
#include <cuda_fp16.h>
#include <cstdint>

#define DIM 256
#define NMOD 5
#define NROWS 16384
#define TB 64
#define NTH 512
#define XPITCH (NMOD * DIM)

#define APITCH 264            // A_s pitch (fp16)
#define BPITCH 72             // B pitch (fp16), 64 K-cols + 8 pad
#define CHUNK_BYTES (256 * BPITCH * 2)   // 36864
#define CHUNK_U16   (CHUNK_BYTES / 16)   // 2304

// Fused per-branch matrices, PRE-PADDED fp16 image: chunk c = n*4+kc holds
// [256 N-rows][72 cols (64 K + 8 pad)] -> contiguous cp.async.
__device__ __align__(16) __half g_M[NMOD * 4][256][BPITCH];
__device__ float g_c[NMOD][DIM];

// ---------------- main-kernel smem layout ----------------
constexpr int SM_GW  = 0;                 // 1792 floats         = 7168
constexpr int SM_GA  = 7168;              // gates 64*8 floats   = 2048
constexpr int SM_RED = 9216;              // 64*8 floats         = 2048
constexpr int SM_ST  = 11264;             // 64 float2           = 512
constexpr int SM_A   = 11776;             // 2 x 64*264*2        = 67584
constexpr int SM_B   = 79360;             // 3 x 36864           = 110592
constexpr int SMEM_TOTAL = SM_B + 3 * CHUNK_BYTES;   // 189952

// ---------------- helpers ----------------
__device__ __forceinline__ void ldsm_x4(uint32_t* r, const void* p) {
    uint32_t addr = (uint32_t)__cvta_generic_to_shared(p);
    asm volatile("ldmatrix.sync.aligned.m8n8.x4.shared.b16 {%0,%1,%2,%3}, [%4];"
                 : "=r"(r[0]), "=r"(r[1]), "=r"(r[2]), "=r"(r[3]) : "r"(addr));
}
// fp16 inputs, fp32 accumulate (prologue)
__device__ __forceinline__ void mma16816f(float* d, const uint32_t* a, const uint32_t* b) {
    asm volatile("mma.sync.aligned.m16n8k16.row.col.f32.f16.f16.f32 "
                 "{%0,%1,%2,%3},{%4,%5,%6,%7},{%8,%9},{%0,%1,%2,%3};"
                 : "+f"(d[0]), "+f"(d[1]), "+f"(d[2]), "+f"(d[3])
                 : "r"(a[0]), "r"(a[1]), "r"(a[2]), "r"(a[3]), "r"(b[0]), "r"(b[1]));
}
// fp16 inputs, fp16 accumulate (main GEMM) — d = 2 x f16x2 regs
__device__ __forceinline__ void mma16816h(uint32_t* d, const uint32_t* a, const uint32_t* b) {
    asm volatile("mma.sync.aligned.m16n8k16.row.col.f16.f16.f16.f16 "
                 "{%0,%1},{%2,%3,%4,%5},{%6,%7},{%0,%1};"
                 : "+r"(d[0]), "+r"(d[1])
                 : "r"(a[0]), "r"(a[1]), "r"(a[2]), "r"(a[3]), "r"(b[0]), "r"(b[1]));
}
__device__ __forceinline__ float warp_sum(float v) {
#pragma unroll
    for (int o = 16; o; o >>= 1) v += __shfl_xor_sync(0xffffffffu, v, o);
    return v;
}
__device__ __forceinline__ void cp_async16(void* smem, const void* g) {
    uint32_t s = (uint32_t)__cvta_generic_to_shared(smem);
    asm volatile("cp.async.cg.shared.global [%0], [%1], 16;\n" :: "r"(s), "l"(g));
}
__device__ __forceinline__ void cp_commit() { asm volatile("cp.async.commit_group;\n"); }
#define BARG(id) asm volatile("bar.sync %0, 128;" :: "r"(id) : "memory")

__device__ __forceinline__ uint32_t pkh2(float a, float b) {
    __half2 h = __floats2half2_rn(a, b);
    return *(uint32_t*)&h;
}

// ------------------------------------------------------------------
// prologue: M_n = Wo_n @ Wv_n (fp16 mma, f32 accum) -> padded image; c_n bias.
// grid (8, 5): bx = 32-row d-block, by = n.  256 threads, warp tile 16x64.
// ------------------------------------------------------------------
__global__ __launch_bounds__(256, 1)
void fuse_weights_kernel(const float* __restrict__ sWi, const float* __restrict__ sbi,
                         const float* __restrict__ sWo, const float* __restrict__ sbo,
                         const float* __restrict__ cWi, const float* __restrict__ cbi,
                         const float* __restrict__ cWo, const float* __restrict__ cbo) {
    extern __shared__ char sm[];
    __half* A_s = (__half*)sm;                       // [32][APITCH]
    __half* B_s = (__half*)(sm + 16896);             // [256][BPITCH]
    float* bv_s = (float*)(sm + 16896 + 36864);
    float* bred = (float*)B_s;

    const int n = blockIdx.y, bx = blockIdx.x;
    const float* Wo = (n == 0) ? sWo : cWo + (size_t)(n - 1) * DIM * DIM;
    const float* Wv = (n == 0) ? sWi + 2 * DIM * DIM
                               : cWi + (size_t)(n - 1) * 3 * DIM * DIM + 2 * DIM * DIM;
    const float* bv = (n == 0) ? sbi + 2 * DIM : cbi + (size_t)(n - 1) * 3 * DIM + 2 * DIM;
    const float* bo = (n == 0) ? sbo : cbo + (size_t)(n - 1) * DIM;

    const int tid = threadIdx.x;
    const int w = tid >> 5, l = tid & 31;
    const int wm = w & 1, wn = w >> 1;
    const int lq = l >> 2, lr = l & 3;

    bv_s[tid] = bv[tid];
#pragma unroll
    for (int i = 0; i < 8; i++) {
        int e = tid + i * 256, r = e >> 6, c4 = (e & 63) << 2;
        float4 v = *(const float4*)(Wo + (size_t)(bx * 32 + r) * DIM + c4);
        __half* dst = A_s + r * APITCH + c4;
        *(uint32_t*)(dst)     = pkh2(v.x, v.y);
        *(uint32_t*)(dst + 2) = pkh2(v.z, v.w);
    }

    float cf[8][4];
#pragma unroll
    for (int nt = 0; nt < 8; nt++)
#pragma unroll
        for (int i = 0; i < 4; i++) cf[nt][i] = 0.f;

#pragma unroll 1
    for (int kc = 0; kc < 4; kc++) {
        __syncthreads();
        int jc = kc * 64;
#pragma unroll
        for (int i = 0; i < 16; i++) {
            int e = tid + i * 256;
            int k = e & 255, j4 = (e >> 8) << 2;
            float v0 = Wv[(size_t)(jc + j4 + 0) * DIM + k];
            float v1 = Wv[(size_t)(jc + j4 + 1) * DIM + k];
            float v2 = Wv[(size_t)(jc + j4 + 2) * DIM + k];
            float v3 = Wv[(size_t)(jc + j4 + 3) * DIM + k];
            __half* dst = B_s + k * BPITCH + j4;
            *(uint32_t*)(dst)     = pkh2(v0, v1);
            *(uint32_t*)(dst + 2) = pkh2(v2, v3);
        }
        __syncthreads();
#pragma unroll
        for (int ks = 0; ks < 4; ks++) {
            uint32_t af[4];
            {
                int row = wm * 16 + (l & 7) + ((l >> 3) & 1) * 8;
                int col = kc * 64 + ks * 16 + (l >> 4) * 8;
                ldsm_x4(af, A_s + row * APITCH + col);
            }
            uint32_t bfr[8][2];
#pragma unroll
            for (int np = 0; np < 4; np++) {
                int row = wn * 64 + np * 16 + (l & 7) + (l >> 4) * 8;
                int col = ks * 16 + ((l >> 3) & 1) * 8;
                uint32_t r4[4];
                ldsm_x4(r4, B_s + row * BPITCH + col);
                bfr[2 * np][0] = r4[0]; bfr[2 * np][1] = r4[1];
                bfr[2 * np + 1][0] = r4[2]; bfr[2 * np + 1][1] = r4[3];
            }
#pragma unroll
            for (int nt = 0; nt < 8; nt++)
                mma16816f(cf[nt], af, bfr[nt]);
        }
    }
    __syncthreads();

    // store to padded fp16 image: chunk = n*4 + (k>>6), row = d, col = k&63
#pragma unroll
    for (int nt = 0; nt < 8; nt++) {
        int d = bx * 32 + wm * 16 + lq;
        int k = wn * 64 + nt * 8 + 2 * lr;
        int ch = n * 4 + (k >> 6);
        int col = k & 63;
        *(uint32_t*)&g_M[ch][d][col]     = pkh2(cf[nt][0], cf[nt][1]);
        *(uint32_t*)&g_M[ch][d + 8][col] = pkh2(cf[nt][2], cf[nt][3]);
    }

    // bias: c[d] = Wo[d,:] @ bv + bo[d]
    {
        int row = tid & 31, part = tid >> 5;
        float s = 0.f;
#pragma unroll 8
        for (int j = 0; j < 32; j++) {
            int jj = part * 32 + j;
            s += __half2float(A_s[row * APITCH + jj]) * bv_s[jj];
        }
        bred[part * 32 + row] = s;
        __syncthreads();
        if (tid < 32) {
            float c = bo[bx * 32 + tid];
#pragma unroll
            for (int p = 0; p < 8; p++) c += bred[p * 32 + tid];
            g_c[n][bx * 32 + tid] = c;
        }
    }
}

// ------------------------------------------------------------------
// main fused kernel (R9 structure, fp16 + f16-accum MMA):
// 64 rows/CTA, 512 threads (16 warps, 4Mx4N, warp 16x64), 3-stage B ring,
// double-buffered A overlapped into epilogue, named-barrier LN reductions.
// f16 accumulation within each 64-K chunk, fp32 across chunks.
// ------------------------------------------------------------------
__global__ __launch_bounds__(NTH, 1)
void fused_main_kernel(const float* __restrict__ x,
                       const float* __restrict__ cross_ln_g, const float* __restrict__ cross_ln_b,
                       const float* __restrict__ gate_ln_g, const float* __restrict__ gate_ln_b,
                       const float* __restrict__ gate_W, const float* __restrict__ gate_b,
                       const float* __restrict__ final_ln_g, const float* __restrict__ final_ln_b,
                       const int* __restrict__ modal_idx, float* __restrict__ out) {
    extern __shared__ char sm[];
    float* gw_s    = (float*)(sm + SM_GW);
    float* gates_s = (float*)(sm + SM_GA);
    float* red_s   = (float*)(sm + SM_RED);
    float2* stat_s = (float2*)(sm + SM_ST);
    __half* A_s    = (__half*)(sm + SM_A);     // [2][64][APITCH]
    char* B_s      = sm + SM_B;                // [3][CHUNK_BYTES]

    const int tid = threadIdx.x;
    const int w = tid >> 5, l = tid & 31;
    const int wm = w & 3, wn = w >> 2;
    const int lq = l >> 2, lr = l & 3;
    const int mi = *modal_idx;
    const int r0 = blockIdx.x * TB;
    const int barid = 1 + wm;

    // prefetch B chunks 0,1 (contiguous image copies)
    {
        const char* src = (const char*)g_M;
#pragma unroll
        for (int i = 0; i < 5; i++) {
            int e = tid + i * NTH;
            if (e < CHUNK_U16) cp_async16(B_s + e * 16, src + e * 16);
        }
        cp_commit();
#pragma unroll
        for (int i = 0; i < 5; i++) {
            int e = tid + i * NTH;
            if (e < CHUNK_U16) cp_async16(B_s + CHUNK_BYTES + e * 16, src + CHUNK_BYTES + e * 16);
        }
        cp_commit();
    }

    // gate constants + A0 fill (branch 0 = modality mi)
    for (int i = tid; i < 1792; i += NTH)
        gw_s[i] = (i < 1280) ? gate_W[i] : (i < 1536 ? gate_ln_g[i - 1280] : gate_ln_b[i - 1536]);
#pragma unroll
    for (int i = 0; i < 8; i++) {
        int e = tid + i * NTH, r = e >> 6, c4 = (e & 63) << 2;
        float4 v = *(const float4*)(x + (size_t)(r0 + r) * XPITCH + mi * DIM + c4);
        __half* dst = A_s + r * APITCH + c4;
        *(uint32_t*)(dst)     = pkh2(v.x, v.y);
        *(uint32_t*)(dst + 2) = pkh2(v.z, v.w);
    }
    __syncthreads();

    // ---- gates: softmax(LN(q) @ gate_W^T + gate_b), warp per 4 rows ----
    {
        float gb[5];
#pragma unroll
        for (int n = 0; n < 5; n++) gb[n] = gate_b[n];
#pragma unroll 1
        for (int ri = 0; ri < 4; ri++) {
            int r = w * 4 + ri;
            const float* xr = x + (size_t)(r0 + r) * XPITCH + mi * DIM;
            float qv[8], sum = 0.f, sq = 0.f;
#pragma unroll
            for (int j = 0; j < 8; j++) {
                qv[j] = xr[l + 32 * j];
                sum += qv[j]; sq += qv[j] * qv[j];
            }
            sum = warp_sum(sum); sq = warp_sum(sq);
            float m = sum * (1.f / DIM);
            float rs = rsqrtf(fmaxf(sq * (1.f / DIM) - m * m, 0.f) + 1e-5f);
            float lnv[8];
#pragma unroll
            for (int j = 0; j < 8; j++) {
                int c = l + 32 * j;
                lnv[j] = (qv[j] - m) * rs * gw_s[1280 + c] + gw_s[1536 + c];
            }
            float lg[5];
#pragma unroll
            for (int n = 0; n < 5; n++) {
                float s = 0.f;
#pragma unroll
                for (int j = 0; j < 8; j++) s += lnv[j] * gw_s[n * DIM + l + 32 * j];
                lg[n] = warp_sum(s) + gb[n];
            }
            float mx = lg[0];
#pragma unroll
            for (int n = 1; n < 5; n++) mx = fmaxf(mx, lg[n]);
            float es = 0.f;
#pragma unroll
            for (int n = 0; n < 5; n++) { lg[n] = expf(lg[n] - mx); es += lg[n]; }
            if (l == 0) {
                float inv = 1.f / es;
#pragma unroll
                for (int n = 0; n < 5; n++) gates_s[r * 8 + n] = lg[n] * inv;
            }
        }
    }

    float acc[8][4];

#pragma unroll 1
    for (int n = 0; n < NMOD; n++) {
        float cf[8][4];
#pragma unroll
        for (int nt = 0; nt < 8; nt++)
#pragma unroll
            for (int i = 0; i < 4; i++) cf[nt][i] = 0.f;

        const __half* As = A_s + (n & 1) * (TB * APITCH);

#pragma unroll 1
        for (int kc = 0; kc < 4; kc++) {
            int c = n * 4 + kc;
            if (c < 19) asm volatile("cp.async.wait_group 1;\n");
            else        asm volatile("cp.async.wait_group 0;\n");
            __syncthreads();   // chunk c visible; ring slot (c+2)%3 free; A/gates visible
            if (c + 2 < 20) {
                const char* src = (const char*)g_M + (size_t)(c + 2) * CHUNK_BYTES;
                char* dst = B_s + ((c + 2) % 3) * CHUNK_BYTES;
#pragma unroll
                for (int i = 0; i < 5; i++) {
                    int e = tid + i * NTH;
                    if (e < CHUNK_U16) cp_async16(dst + e * 16, src + e * 16);
                }
                cp_commit();
            }
            const __half* Bc = (const __half*)(B_s + (c % 3) * CHUNK_BYTES);

            // f16-accum fragments for this chunk
            uint32_t hacc[8][2];
#pragma unroll
            for (int nt = 0; nt < 8; nt++) { hacc[nt][0] = 0u; hacc[nt][1] = 0u; }

#pragma unroll
            for (int ks = 0; ks < 4; ks++) {
                uint32_t af[4];
                {
                    int row = wm * 16 + (l & 7) + ((l >> 3) & 1) * 8;
                    int col = kc * 64 + ks * 16 + (l >> 4) * 8;
                    ldsm_x4(af, As + row * APITCH + col);
                }
                uint32_t bfr[8][2];
#pragma unroll
                for (int np = 0; np < 4; np++) {
                    int row = wn * 64 + np * 16 + (l & 7) + (l >> 4) * 8;
                    int col = ks * 16 + ((l >> 3) & 1) * 8;
                    uint32_t r4[4];
                    ldsm_x4(r4, Bc + row * BPITCH + col);
                    bfr[2 * np][0] = r4[0]; bfr[2 * np][1] = r4[1];
                    bfr[2 * np + 1][0] = r4[2]; bfr[2 * np + 1][1] = r4[3];
                }
#pragma unroll
                for (int nt = 0; nt < 8; nt++)
                    mma16816h(hacc[nt], af, bfr[nt]);
            }
            // promote chunk partials to fp32
#pragma unroll
            for (int nt = 0; nt < 8; nt++) {
                float2 lo = __half22float2(*(__half2*)&hacc[nt][0]);
                float2 hi = __half22float2(*(__half2*)&hacc[nt][1]);
                cf[nt][0] += lo.x; cf[nt][1] += lo.y;
                cf[nt][2] += hi.x; cf[nt][3] += hi.y;
            }
        }

        // fill A for branch n+1 (LDG latency hides under epilogue)
        if (n + 1 < NMOD) {
            int m2 = n + 1;
            int mod = ((m2 - 1) < mi) ? (m2 - 1) : m2;
            __half* Ad = A_s + (m2 & 1) * (TB * APITCH);
#pragma unroll
            for (int i = 0; i < 8; i++) {
                int e = tid + i * NTH, r = e >> 6, c4 = (e & 63) << 2;
                float4 v = *(const float4*)(x + (size_t)(r0 + r) * XPITCH + mod * DIM + c4);
                __half* dst = Ad + r * APITCH + c4;
                *(uint32_t*)(dst)     = pkh2(v.x, v.y);
                *(uint32_t*)(dst + 2) = pkh2(v.z, v.w);
            }
        }

        // ---- epilogue (fragment layout) ----
        if (n == 0) {
#pragma unroll
            for (int half = 0; half < 2; half++) {
                int row = wm * 16 + lq + half * 8;
                float g0 = gates_s[row * 8 + 0];
#pragma unroll
                for (int nt = 0; nt < 8; nt++) {
                    float2 c2 = *(const float2*)(g_c[0] + wn * 64 + nt * 8 + 2 * lr);
                    acc[nt][2 * half + 0] = g0 * (cf[nt][2 * half + 0] + c2.x);
                    acc[nt][2 * half + 1] = g0 * (cf[nt][2 * half + 1] + c2.y);
                }
            }
        } else {
            float sums[2], sqs[2];
#pragma unroll
            for (int half = 0; half < 2; half++) {
                int row = wm * 16 + lq + half * 8;
                const float* qr = x + (size_t)(r0 + row) * XPITCH + mi * DIM + wn * 64;
                float s = 0.f, ss = 0.f;
#pragma unroll
                for (int nt = 0; nt < 8; nt++) {
                    float2 q2 = *(const float2*)(qr + nt * 8 + 2 * lr);
                    float2 c2 = *(const float2*)(g_c[n] + wn * 64 + nt * 8 + 2 * lr);
                    float t0 = q2.x + cf[nt][2 * half + 0] + c2.x;
                    float t1 = q2.y + cf[nt][2 * half + 1] + c2.y;
                    cf[nt][2 * half + 0] = t0;
                    cf[nt][2 * half + 1] = t1;
                    s += t0 + t1; ss += t0 * t0 + t1 * t1;
                }
                s += __shfl_xor_sync(0xffffffffu, s, 1);
                s += __shfl_xor_sync(0xffffffffu, s, 2);
                ss += __shfl_xor_sync(0xffffffffu, ss, 1);
                ss += __shfl_xor_sync(0xffffffffu, ss, 2);
                sums[half] = s; sqs[half] = ss;
            }
            if (lr == 0) {
#pragma unroll
                for (int half = 0; half < 2; half++) {
                    int row = wm * 16 + lq + half * 8;
                    red_s[row * 8 + wn * 2 + 0] = sums[half];
                    red_s[row * 8 + wn * 2 + 1] = sqs[half];
                }
            }
            BARG(barid);
            if (wn == 0 && l < 16) {
                int rr = wm * 16 + l;
                float s = red_s[rr * 8 + 0] + red_s[rr * 8 + 2] + red_s[rr * 8 + 4] + red_s[rr * 8 + 6];
                float ss = red_s[rr * 8 + 1] + red_s[rr * 8 + 3] + red_s[rr * 8 + 5] + red_s[rr * 8 + 7];
                float m = s * (1.f / DIM);
                float var = fmaxf(ss * (1.f / DIM) - m * m, 0.f);
                stat_s[rr] = make_float2(m, rsqrtf(var + 1e-5f));
            }
            BARG(barid);
            const float* gam = cross_ln_g + (n - 1) * DIM + wn * 64;
            const float* bet = cross_ln_b + (n - 1) * DIM + wn * 64;
#pragma unroll
            for (int half = 0; half < 2; half++) {
                int row = wm * 16 + lq + half * 8;
                float2 st = stat_s[row];
                float gn = gates_s[row * 8 + n];
#pragma unroll
                for (int nt = 0; nt < 8; nt++) {
                    float2 g2 = *(const float2*)(gam + nt * 8 + 2 * lr);
                    float2 b2 = *(const float2*)(bet + nt * 8 + 2 * lr);
                    acc[nt][2 * half + 0] +=
                        gn * ((cf[nt][2 * half + 0] - st.x) * st.y * g2.x + b2.x);
                    acc[nt][2 * half + 1] +=
                        gn * ((cf[nt][2 * half + 1] - st.x) * st.y * g2.y + b2.y);
                }
            }
        }
    }

    // ---- final LN(q + acc), store ----
    {
        float sums[2], sqs[2];
#pragma unroll
        for (int half = 0; half < 2; half++) {
            int row = wm * 16 + lq + half * 8;
            const float* qr = x + (size_t)(r0 + row) * XPITCH + mi * DIM + wn * 64;
            float s = 0.f, ss = 0.f;
#pragma unroll
            for (int nt = 0; nt < 8; nt++) {
                float2 q2 = *(const float2*)(qr + nt * 8 + 2 * lr);
                float t0 = q2.x + acc[nt][2 * half + 0];
                float t1 = q2.y + acc[nt][2 * half + 1];
                acc[nt][2 * half + 0] = t0;
                acc[nt][2 * half + 1] = t1;
                s += t0 + t1; ss += t0 * t0 + t1 * t1;
            }
            s += __shfl_xor_sync(0xffffffffu, s, 1);
            s += __shfl_xor_sync(0xffffffffu, s, 2);
            ss += __shfl_xor_sync(0xffffffffu, ss, 1);
            ss += __shfl_xor_sync(0xffffffffu, ss, 2);
            sums[half] = s; sqs[half] = ss;
        }
        if (lr == 0) {
#pragma unroll
            for (int half = 0; half < 2; half++) {
                int row = wm * 16 + lq + half * 8;
                red_s[row * 8 + wn * 2 + 0] = sums[half];
                red_s[row * 8 + wn * 2 + 1] = sqs[half];
            }
        }
        BARG(barid);
        if (wn == 0 && l < 16) {
            int rr = wm * 16 + l;
            float s = red_s[rr * 8 + 0] + red_s[rr * 8 + 2] + red_s[rr * 8 + 4] + red_s[rr * 8 + 6];
            float ss = red_s[rr * 8 + 1] + red_s[rr * 8 + 3] + red_s[rr * 8 + 5] + red_s[rr * 8 + 7];
            float m = s * (1.f / DIM);
            float var = fmaxf(ss * (1.f / DIM) - m * m, 0.f);
            stat_s[rr] = make_float2(m, rsqrtf(var + 1e-5f));
        }
        BARG(barid);
        const float* fg = final_ln_g + wn * 64;
        const float* fb = final_ln_b + wn * 64;
#pragma unroll
        for (int half = 0; half < 2; half++) {
            int row = wm * 16 + lq + half * 8;
            float2 st = stat_s[row];
            float* orow = out + (size_t)(r0 + row) * DIM + wn * 64;
#pragma unroll
            for (int nt = 0; nt < 8; nt++) {
                float2 g2 = *(const float2*)(fg + nt * 8 + 2 * lr);
                float2 b2 = *(const float2*)(fb + nt * 8 + 2 * lr);
                float o0 = (acc[nt][2 * half + 0] - st.x) * st.y * g2.x + b2.x;
                float o1 = (acc[nt][2 * half + 1] - st.x) * st.y * g2.y + b2.y;
                *(float2*)(orow + nt * 8 + 2 * lr) = make_float2(o0, o1);
            }
        }
    }
}

// ------------------------------------------------------------------
extern "C" void kernel_launch(void* const* d_in, const int* in_sizes, int n_in,
                              void* d_out, int out_size) {
    (void)in_sizes; (void)n_in; (void)out_size;
    const float* x          = (const float*)d_in[0];
    const float* self_Wi    = (const float*)d_in[1];
    const float* self_bi    = (const float*)d_in[2];
    const float* self_Wo    = (const float*)d_in[3];
    const float* self_bo    = (const float*)d_in[4];
    const float* cross_Wi   = (const float*)d_in[5];
    const float* cross_bi   = (const float*)d_in[6];
    const float* cross_Wo   = (const float*)d_in[7];
    const float* cross_bo   = (const float*)d_in[8];
    const float* cross_ln_g = (const float*)d_in[9];
    const float* cross_ln_b = (const float*)d_in[10];
    const float* gate_ln_g  = (const float*)d_in[11];
    const float* gate_ln_b  = (const float*)d_in[12];
    const float* gate_W     = (const float*)d_in[13];
    const float* gate_b     = (const float*)d_in[14];
    const float* final_ln_g = (const float*)d_in[15];
    const float* final_ln_b = (const float*)d_in[16];
    const int*   modal_idx  = (const int*)d_in[17];
    float* out = (float*)d_out;

    static bool attr_set = false;
    if (!attr_set) {
        cudaFuncSetAttribute(fused_main_kernel,
                             cudaFuncAttributeMaxDynamicSharedMemorySize, SMEM_TOTAL);
        cudaFuncSetAttribute(fuse_weights_kernel,
                             cudaFuncAttributeMaxDynamicSharedMemorySize, 54784);
        attr_set = true;
    }

    fuse_weights_kernel<<<dim3(8, 5), 256, 54784>>>(self_Wi, self_bi, self_Wo, self_bo,
                                                    cross_Wi, cross_bi, cross_Wo, cross_bo);
    fused_main_kernel<<<NROWS / TB, NTH, SMEM_TOTAL>>>(
        x, cross_ln_g, cross_ln_b, gate_ln_g, gate_ln_b,
        gate_W, gate_b, final_ln_g, final_ln_b, modal_idx, out);
}

// round 13
// speedup vs baseline: 1.2412x; 1.1331x over previous
#include <cuda_runtime.h>
#include <cuda_fp16.h>
#include <cstdint>

#define DIM 256
#define NMOD 5
#define NROWS 16384
#define TB 64
#define NTH 512
#define XPITCH (NMOD * DIM)

#define APITCH 264            // A_s pitch (fp16)
#define BPITCH 72             // B pitch (fp16), 64 K-cols + 8 pad
#define SPITCH 264            // stage pitch (fp32)
#define CHUNK_BYTES (256 * BPITCH * 2)   // 36864
#define CHUNK_U16   (CHUNK_BYTES / 16)   // 2304

// Fused per-branch matrices, PRE-PADDED fp16 image (chunk c = n*4+kc).
__device__ __align__(16) __half g_M[NMOD * 4][256][BPITCH];
__device__ float g_c[NMOD][DIM];

// ---------------- main-kernel smem layout ----------------
constexpr int SM_GW  = 0;                        // 1792 floats      = 7168
constexpr int SM_GA  = 7168;                     // gates 64*8 f     = 2048
constexpr int SM_STG = 9216;                     // 64*264 fp32      = 67584
constexpr int SM_A   = SM_STG + 67584;           // 2 x 64*264 fp16  = 67584
constexpr int SM_B   = SM_A + 67584;             // 2 x 36864        = 73728
constexpr int SMEM_TOTAL = SM_B + 73728;         // 218112

// named barriers
#define BID_AREADY 1
#define BID_SFULL  2
#define BID_SFREE  3
#define BID_PROD   6
#define BID_CONS   7
#define BAR_SYNC(id, cnt)   asm volatile("bar.sync %0, %1;"   :: "r"(id), "r"(cnt) : "memory")
#define BAR_ARRIVE(id, cnt) asm volatile("bar.arrive %0, %1;" :: "r"(id), "r"(cnt) : "memory")

// ---------------- helpers ----------------
__device__ __forceinline__ void ldsm_x4(uint32_t* r, const void* p) {
    uint32_t addr = (uint32_t)__cvta_generic_to_shared(p);
    asm volatile("ldmatrix.sync.aligned.m8n8.x4.shared.b16 {%0,%1,%2,%3}, [%4];"
                 : "=r"(r[0]), "=r"(r[1]), "=r"(r[2]), "=r"(r[3]) : "r"(addr));
}
__device__ __forceinline__ void mma16816f(float* d, const uint32_t* a, const uint32_t* b) {
    asm volatile("mma.sync.aligned.m16n8k16.row.col.f32.f16.f16.f32 "
                 "{%0,%1,%2,%3},{%4,%5,%6,%7},{%8,%9},{%0,%1,%2,%3};"
                 : "+f"(d[0]), "+f"(d[1]), "+f"(d[2]), "+f"(d[3])
                 : "r"(a[0]), "r"(a[1]), "r"(a[2]), "r"(a[3]), "r"(b[0]), "r"(b[1]));
}
__device__ __forceinline__ float warp_sum(float v) {
#pragma unroll
    for (int o = 16; o; o >>= 1) v += __shfl_xor_sync(0xffffffffu, v, o);
    return v;
}
__device__ __forceinline__ void cp_async16(void* smem, const void* g) {
    uint32_t s = (uint32_t)__cvta_generic_to_shared(smem);
    asm volatile("cp.async.cg.shared.global [%0], [%1], 16;\n" :: "r"(s), "l"(g));
}
__device__ __forceinline__ void cp_commit() { asm volatile("cp.async.commit_group;\n"); }
__device__ __forceinline__ uint32_t pkh2(float a, float b) {
    __half2 h = __floats2half2_rn(a, b);
    return *(uint32_t*)&h;
}

// ------------------------------------------------------------------
// prologue (unchanged from R12): M_n = Wo_n @ Wv_n (fp16 mma, f32 accum)
// -> padded fp16 image; c_n bias. grid (8,5), 256 threads.
// ------------------------------------------------------------------
__global__ __launch_bounds__(256, 1)
void fuse_weights_kernel(const float* __restrict__ sWi, const float* __restrict__ sbi,
                         const float* __restrict__ sWo, const float* __restrict__ sbo,
                         const float* __restrict__ cWi, const float* __restrict__ cbi,
                         const float* __restrict__ cWo, const float* __restrict__ cbo) {
    extern __shared__ char sm[];
    __half* A_s = (__half*)sm;                       // [32][APITCH]
    __half* B_s = (__half*)(sm + 16896);             // [256][BPITCH]
    float* bv_s = (float*)(sm + 16896 + 36864);
    float* bred = (float*)B_s;

    const int n = blockIdx.y, bx = blockIdx.x;
    const float* Wo = (n == 0) ? sWo : cWo + (size_t)(n - 1) * DIM * DIM;
    const float* Wv = (n == 0) ? sWi + 2 * DIM * DIM
                               : cWi + (size_t)(n - 1) * 3 * DIM * DIM + 2 * DIM * DIM;
    const float* bv = (n == 0) ? sbi + 2 * DIM : cbi + (size_t)(n - 1) * 3 * DIM + 2 * DIM;
    const float* bo = (n == 0) ? sbo : cbo + (size_t)(n - 1) * DIM;

    const int tid = threadIdx.x;
    const int w = tid >> 5, l = tid & 31;
    const int wm = w & 1, wn = w >> 1;
    const int lq = l >> 2, lr = l & 3;

    bv_s[tid] = bv[tid];
#pragma unroll
    for (int i = 0; i < 8; i++) {
        int e = tid + i * 256, r = e >> 6, c4 = (e & 63) << 2;
        float4 v = *(const float4*)(Wo + (size_t)(bx * 32 + r) * DIM + c4);
        __half* dst = A_s + r * APITCH + c4;
        *(uint32_t*)(dst)     = pkh2(v.x, v.y);
        *(uint32_t*)(dst + 2) = pkh2(v.z, v.w);
    }

    float cf[8][4];
#pragma unroll
    for (int nt = 0; nt < 8; nt++)
#pragma unroll
        for (int i = 0; i < 4; i++) cf[nt][i] = 0.f;

#pragma unroll 1
    for (int kc = 0; kc < 4; kc++) {
        __syncthreads();
        int jc = kc * 64;
#pragma unroll
        for (int i = 0; i < 16; i++) {
            int e = tid + i * 256;
            int k = e & 255, j4 = (e >> 8) << 2;
            float v0 = Wv[(size_t)(jc + j4 + 0) * DIM + k];
            float v1 = Wv[(size_t)(jc + j4 + 1) * DIM + k];
            float v2 = Wv[(size_t)(jc + j4 + 2) * DIM + k];
            float v3 = Wv[(size_t)(jc + j4 + 3) * DIM + k];
            __half* dst = B_s + k * BPITCH + j4;
            *(uint32_t*)(dst)     = pkh2(v0, v1);
            *(uint32_t*)(dst + 2) = pkh2(v2, v3);
        }
        __syncthreads();
#pragma unroll
        for (int ks = 0; ks < 4; ks++) {
            uint32_t af[4];
            {
                int row = wm * 16 + (l & 7) + ((l >> 3) & 1) * 8;
                int col = kc * 64 + ks * 16 + (l >> 4) * 8;
                ldsm_x4(af, A_s + row * APITCH + col);
            }
            uint32_t bfr[8][2];
#pragma unroll
            for (int np = 0; np < 4; np++) {
                int row = wn * 64 + np * 16 + (l & 7) + (l >> 4) * 8;
                int col = ks * 16 + ((l >> 3) & 1) * 8;
                uint32_t r4[4];
                ldsm_x4(r4, B_s + row * BPITCH + col);
                bfr[2 * np][0] = r4[0]; bfr[2 * np][1] = r4[1];
                bfr[2 * np + 1][0] = r4[2]; bfr[2 * np + 1][1] = r4[3];
            }
#pragma unroll
            for (int nt = 0; nt < 8; nt++)
                mma16816f(cf[nt], af, bfr[nt]);
        }
    }
    __syncthreads();

#pragma unroll
    for (int nt = 0; nt < 8; nt++) {
        int d = bx * 32 + wm * 16 + lq;
        int k = wn * 64 + nt * 8 + 2 * lr;
        int ch = n * 4 + (k >> 6);
        int col = k & 63;
        *(uint32_t*)&g_M[ch][d][col]     = pkh2(cf[nt][0], cf[nt][1]);
        *(uint32_t*)&g_M[ch][d + 8][col] = pkh2(cf[nt][2], cf[nt][3]);
    }

    {
        int row = tid & 31, part = tid >> 5;
        float s = 0.f;
#pragma unroll 8
        for (int j = 0; j < 32; j++) {
            int jj = part * 32 + j;
            s += __half2float(A_s[row * APITCH + jj]) * bv_s[jj];
        }
        bred[part * 32 + row] = s;
        __syncthreads();
        if (tid < 32) {
            float c = bo[bx * 32 + tid];
#pragma unroll
            for (int p = 0; p < 8; p++) c += bred[p * 32 + tid];
            g_c[n][bx * 32 + tid] = c;
        }
    }
}

// ------------------------------------------------------------------
// main kernel: warp-specialized producer/consumer.
// 64 rows/CTA, 512 threads: warps 0-7 = GEMM producers (2Mx4N, 32x64 tile),
// warps 8-15 = epilogue consumers (8 rows each, warp-private LN).
// Handshake: named barriers A_READY / STG_FULL / STG_FREE.
// ------------------------------------------------------------------
__global__ __launch_bounds__(NTH, 1)
void fused_main_kernel(const float* __restrict__ x,
                       const float* __restrict__ cross_ln_g, const float* __restrict__ cross_ln_b,
                       const float* __restrict__ gate_ln_g, const float* __restrict__ gate_ln_b,
                       const float* __restrict__ gate_W, const float* __restrict__ gate_b,
                       const float* __restrict__ final_ln_g, const float* __restrict__ final_ln_b,
                       const int* __restrict__ modal_idx, float* __restrict__ out) {
    extern __shared__ char sm[];
    float* gw_s    = (float*)(sm + SM_GW);      // gate_W 1280 | ln_g 256 | ln_b 256
    float* gates_s = (float*)(sm + SM_GA);      // [64][8]
    float* stg     = (float*)(sm + SM_STG);     // [64][SPITCH] fp32
    __half* A_s    = (__half*)(sm + SM_A);      // [2][64][APITCH]
    char* B_s      = sm + SM_B;                 // [2][CHUNK_BYTES]

    const int tid = threadIdx.x;
    const int w = tid >> 5, l = tid & 31;
    const int mi = *modal_idx;
    const int r0 = blockIdx.x * TB;

    // producers issue B prefetch (chunks 0,1)
    if (tid < 256) {
        const char* src = (const char*)g_M;
#pragma unroll
        for (int i = 0; i < 9; i++) {
            int e = tid + i * 256;
            if (e < CHUNK_U16) cp_async16(B_s + e * 16, src + e * 16);
        }
        cp_commit();
#pragma unroll
        for (int i = 0; i < 9; i++) {
            int e = tid + i * 256;
            if (e < CHUNK_U16) cp_async16(B_s + CHUNK_BYTES + e * 16, src + CHUNK_BYTES + e * 16);
        }
        cp_commit();
    }

    // A0 fill by all 512 threads (branch 0 = modality mi)
#pragma unroll
    for (int i = 0; i < 8; i++) {
        int e = tid + i * NTH, r = e >> 6, c4 = (e & 63) << 2;
        float4 v = *(const float4*)(x + (size_t)(r0 + r) * XPITCH + mi * DIM + c4);
        __half* dst = A_s + r * APITCH + c4;
        *(uint32_t*)(dst)     = pkh2(v.x, v.y);
        *(uint32_t*)(dst + 2) = pkh2(v.z, v.w);
    }
    __syncthreads();

    if (w < 8) {
        // ===================== PRODUCER (8 warps) =====================
        const int wm = w & 1, wn = w >> 1;
        const int lq = l >> 2, lr = l & 3;

#pragma unroll 1
        for (int n = 0; n < NMOD; n++) {
            if (n) BAR_SYNC(BID_AREADY, 512);     // A[n&1] filled by consumers
            const __half* As = A_s + (n & 1) * (TB * APITCH);

            float cf[2][8][4];
#pragma unroll
            for (int mt = 0; mt < 2; mt++)
#pragma unroll
                for (int nt = 0; nt < 8; nt++)
#pragma unroll
                    for (int i = 0; i < 4; i++) cf[mt][nt][i] = 0.f;

#pragma unroll 1
            for (int kc = 0; kc < 4; kc++) {
                int c = n * 4 + kc;
                asm volatile("cp.async.wait_group 0;\n");
                BAR_SYNC(BID_PROD, 256);          // chunk c visible; old buf free
                if (c + 1 < 20) {
                    const char* src = (const char*)g_M + (size_t)(c + 1) * CHUNK_BYTES;
                    char* dst = B_s + ((c + 1) & 1) * CHUNK_BYTES;
#pragma unroll
                    for (int i = 0; i < 9; i++) {
                        int e = tid + i * 256;
                        if (e < CHUNK_U16) cp_async16(dst + e * 16, src + e * 16);
                    }
                    cp_commit();
                }
                const __half* Bc = (const __half*)(B_s + (c & 1) * CHUNK_BYTES);
#pragma unroll
                for (int ks = 0; ks < 4; ks++) {
                    uint32_t af[2][4];
#pragma unroll
                    for (int mt = 0; mt < 2; mt++) {
                        int row = wm * 32 + mt * 16 + (l & 7) + ((l >> 3) & 1) * 8;
                        int col = kc * 64 + ks * 16 + (l >> 4) * 8;
                        ldsm_x4(af[mt], As + row * APITCH + col);
                    }
                    uint32_t bfr[8][2];
#pragma unroll
                    for (int np = 0; np < 4; np++) {
                        int row = wn * 64 + np * 16 + (l & 7) + (l >> 4) * 8;
                        int col = ks * 16 + ((l >> 3) & 1) * 8;
                        uint32_t r4[4];
                        ldsm_x4(r4, Bc + row * BPITCH + col);
                        bfr[2 * np][0] = r4[0]; bfr[2 * np][1] = r4[1];
                        bfr[2 * np + 1][0] = r4[2]; bfr[2 * np + 1][1] = r4[3];
                    }
#pragma unroll
                    for (int mt = 0; mt < 2; mt++)
#pragma unroll
                        for (int nt = 0; nt < 8; nt++)
                            mma16816f(cf[mt][nt], af[mt], bfr[nt]);
                }
            }

            // publish a-tile to stage (fp32)
            if (n) BAR_SYNC(BID_SFREE, 512);      // consumers drained stage n-1
#pragma unroll
            for (int mt = 0; mt < 2; mt++)
#pragma unroll
                for (int nt = 0; nt < 8; nt++) {
                    int row = wm * 32 + mt * 16 + lq;
                    int col = wn * 64 + nt * 8 + 2 * lr;
                    *(float2*)(stg + row * SPITCH + col)       = make_float2(cf[mt][nt][0], cf[mt][nt][1]);
                    *(float2*)(stg + (row + 8) * SPITCH + col) = make_float2(cf[mt][nt][2], cf[mt][nt][3]);
                }
            __threadfence_block();
            BAR_ARRIVE(BID_SFULL, 512);
        }
    } else {
        // ===================== CONSUMER (8 warps) =====================
        const int cw = w - 8;            // 0..7, owns rows cw*8 .. cw*8+7
        const int ctid = tid - 256;      // 0..255

        for (int i = ctid; i < 1792; i += 256)
            gw_s[i] = (i < 1280) ? gate_W[i] : (i < 1536 ? gate_ln_g[i - 1280] : gate_ln_b[i - 1536]);
        BAR_SYNC(BID_CONS, 256);

        // gates for my 8 rows (overlaps producer GEMM 0)
        {
            float gb[5];
#pragma unroll
            for (int n = 0; n < 5; n++) gb[n] = gate_b[n];
#pragma unroll 1
            for (int ri = 0; ri < 8; ri++) {
                int r = cw * 8 + ri;
                const float* xr = x + (size_t)(r0 + r) * XPITCH + mi * DIM;
                float qv[8], sum = 0.f, sq = 0.f;
#pragma unroll
                for (int j = 0; j < 8; j++) {
                    qv[j] = xr[l + 32 * j];
                    sum += qv[j]; sq += qv[j] * qv[j];
                }
                sum = warp_sum(sum); sq = warp_sum(sq);
                float m = sum * (1.f / DIM);
                float rs = rsqrtf(fmaxf(sq * (1.f / DIM) - m * m, 0.f) + 1e-5f);
                float lnv[8];
#pragma unroll
                for (int j = 0; j < 8; j++) {
                    int c = l + 32 * j;
                    lnv[j] = (qv[j] - m) * rs * gw_s[1280 + c] + gw_s[1536 + c];
                }
                float lg[5];
#pragma unroll
                for (int n = 0; n < 5; n++) {
                    float s = 0.f;
#pragma unroll
                    for (int j = 0; j < 8; j++) s += lnv[j] * gw_s[n * DIM + l + 32 * j];
                    lg[n] = warp_sum(s) + gb[n];
                }
                float mx = lg[0];
#pragma unroll
                for (int n = 1; n < 5; n++) mx = fmaxf(mx, lg[n]);
                float es = 0.f;
#pragma unroll
                for (int n = 0; n < 5; n++) { lg[n] = expf(lg[n] - mx); es += lg[n]; }
                if (l == 0) {
                    float inv = 1.f / es;
#pragma unroll
                    for (int n = 0; n < 5; n++) gates_s[r * 8 + n] = lg[n] * inv;
                }
            }
            __syncwarp();
        }

        float acc[8][8];

#pragma unroll 1
        for (int n = 0; n < NMOD; n++) {
            // fill A for branch n+1 (buffer (n+1)&1 is free: GEMM n-1 done)
            if (n + 1 < NMOD) {
                int m2 = n + 1;
                int mod = ((m2 - 1) < mi) ? (m2 - 1) : m2;
                __half* Ad = A_s + (m2 & 1) * (TB * APITCH);
#pragma unroll
                for (int i = 0; i < 16; i++) {
                    int e = ctid + i * 256, r = e >> 6, c4 = (e & 63) << 2;
                    float4 v = *(const float4*)(x + (size_t)(r0 + r) * XPITCH + mod * DIM + c4);
                    __half* dst = Ad + r * APITCH + c4;
                    *(uint32_t*)(dst)     = pkh2(v.x, v.y);
                    *(uint32_t*)(dst + 2) = pkh2(v.z, v.w);
                }
                __threadfence_block();
                BAR_ARRIVE(BID_AREADY, 512);
            }

            BAR_SYNC(BID_SFULL, 512);   // stage n ready

            if (n == 0) {
                float c0[8];
#pragma unroll
                for (int j = 0; j < 8; j++) c0[j] = g_c[0][l + 32 * j];
#pragma unroll
                for (int ri = 0; ri < 8; ri++) {
                    int row = cw * 8 + ri;
                    float g0 = gates_s[row * 8 + 0];
#pragma unroll
                    for (int j = 0; j < 8; j++)
                        acc[ri][j] = g0 * (stg[row * SPITCH + l + 32 * j] + c0[j]);
                }
            } else {
                float cn[8], gm[8], bt[8];
                const float* gam = cross_ln_g + (n - 1) * DIM;
                const float* bet = cross_ln_b + (n - 1) * DIM;
#pragma unroll
                for (int j = 0; j < 8; j++) {
                    int c = l + 32 * j;
                    cn[j] = g_c[n][c]; gm[j] = gam[c]; bt[j] = bet[c];
                }
#pragma unroll
                for (int ri = 0; ri < 8; ri++) {
                    int row = cw * 8 + ri;
                    const float* qr = x + (size_t)(r0 + row) * XPITCH + mi * DIM;
                    float t[8], s = 0.f, ss = 0.f;
#pragma unroll
                    for (int j = 0; j < 8; j++) {
                        t[j] = qr[l + 32 * j] + stg[row * SPITCH + l + 32 * j] + cn[j];
                        s += t[j]; ss += t[j] * t[j];
                    }
                    s = warp_sum(s); ss = warp_sum(ss);
                    float m = s * (1.f / DIM);
                    float rs = rsqrtf(fmaxf(ss * (1.f / DIM) - m * m, 0.f) + 1e-5f);
                    float gn = gates_s[row * 8 + n];
#pragma unroll
                    for (int j = 0; j < 8; j++)
                        acc[ri][j] += gn * ((t[j] - m) * rs * gm[j] + bt[j]);
                }
            }

            if (n + 1 < NMOD) BAR_ARRIVE(BID_SFREE, 512);
        }

        // ---- final LN(q + acc), store ----
        {
            float fg[8], fb[8];
#pragma unroll
            for (int j = 0; j < 8; j++) {
                int c = l + 32 * j;
                fg[j] = final_ln_g[c]; fb[j] = final_ln_b[c];
            }
#pragma unroll
            for (int ri = 0; ri < 8; ri++) {
                int row = cw * 8 + ri;
                const float* qr = x + (size_t)(r0 + row) * XPITCH + mi * DIM;
                float tv[8], s = 0.f, ss = 0.f;
#pragma unroll
                for (int j = 0; j < 8; j++) {
                    tv[j] = qr[l + 32 * j] + acc[ri][j];
                    s += tv[j]; ss += tv[j] * tv[j];
                }
                s = warp_sum(s); ss = warp_sum(ss);
                float m = s * (1.f / DIM);
                float rs = rsqrtf(fmaxf(ss * (1.f / DIM) - m * m, 0.f) + 1e-5f);
                float* orow = out + (size_t)(r0 + row) * DIM;
#pragma unroll
                for (int j = 0; j < 8; j++)
                    orow[l + 32 * j] = (tv[j] - m) * rs * fg[j] + fb[j];
            }
        }
    }
}

// ------------------------------------------------------------------
extern "C" void kernel_launch(void* const* d_in, const int* in_sizes, int n_in,
                              void* d_out, int out_size) {
    (void)in_sizes; (void)n_in; (void)out_size;
    const float* x          = (const float*)d_in[0];
    const float* self_Wi    = (const float*)d_in[1];
    const float* self_bi    = (const float*)d_in[2];
    const float* self_Wo    = (const float*)d_in[3];
    const float* self_bo    = (const float*)d_in[4];
    const float* cross_Wi   = (const float*)d_in[5];
    const float* cross_bi   = (const float*)d_in[6];
    const float* cross_Wo   = (const float*)d_in[7];
    const float* cross_bo   = (const float*)d_in[8];
    const float* cross_ln_g = (const float*)d_in[9];
    const float* cross_ln_b = (const float*)d_in[10];
    const float* gate_ln_g  = (const float*)d_in[11];
    const float* gate_ln_b  = (const float*)d_in[12];
    const float* gate_W     = (const float*)d_in[13];
    const float* gate_b     = (const float*)d_in[14];
    const float* final_ln_g = (const float*)d_in[15];
    const float* final_ln_b = (const float*)d_in[16];
    const int*   modal_idx  = (const int*)d_in[17];
    float* out = (float*)d_out;

    static bool attr_set = false;
    if (!attr_set) {
        cudaFuncSetAttribute(fused_main_kernel,
                             cudaFuncAttributeMaxDynamicSharedMemorySize, SMEM_TOTAL);
        cudaFuncSetAttribute(fuse_weights_kernel,
                             cudaFuncAttributeMaxDynamicSharedMemorySize, 54784);
        attr_set = true;
    }

    fuse_weights_kernel<<<dim3(8, 5), 256, 54784>>>(self_Wi, self_bi, self_Wo, self_bo,
                                                    cross_Wi, cross_bi, cross_Wo, cross_bo);
    fused_main_kernel<<<NROWS / TB, NTH, SMEM_TOTAL>>>(
        x, cross_ln_g, cross_ln_b, gate_ln_g, gate_ln_b,
        gate_W, gate_b, final_ln_g, final_ln_b, modal_idx, out);
}